// round 15
// baseline (speedup 1.0000x reference)
#include <cuda_runtime.h>
#include <cuda_bf16.h>
#include <cstdint>

#define T_STEPS 512
#define BATCH   32
#define IDIM    1024
#define HDIM    1024
#define G4      4096   // 4*HDIM
#define GRID_SCAN 128  // all CTAs co-resident (<= SM count)

// Scratch (static device arrays: allowed; no cudaMalloc anywhere)
__device__ float    g_gates[(size_t)T_STEPS * BATCH * G4];   // [t*B+b][g] (256 MB)
__device__ float    g_part[4 * BATCH * HDIM * 4];            // [kc][b][h][gate] (2 MB)
__device__ uint16_t g_yhi[BATCH * HDIM];                     // y as bf16 hi
__device__ uint16_t g_ylo[BATCH * HDIM];                     // y as bf16 lo

// Grid-barrier state (sense-reversing; even barrier count per launch -> clean replays)
__device__ int               g_bar_count = 0;
__device__ volatile unsigned g_bar_sense = 0;

__device__ __forceinline__ float hsig(float x) {
    return fminf(fmaxf(x * (1.0f / 6.0f) + 0.5f, 0.0f), 1.0f);
}
__device__ __forceinline__ float htanh(float x) {
    return fminf(fmaxf(x, -1.0f), 1.0f);
}

// Split two floats into packed bf16 hi-pair and lo-pair (v = hi + lo)
__device__ __forceinline__ void split2(float x, float y, uint32_t& hi, uint32_t& lo) {
    const __nv_bfloat16 hx = __float2bfloat16_rn(x);
    const __nv_bfloat16 hy = __float2bfloat16_rn(y);
    const float fx = __bfloat162float(hx);
    const float fy = __bfloat162float(hy);
    const __nv_bfloat16 lx = __float2bfloat16_rn(x - fx);
    const __nv_bfloat16 ly = __float2bfloat16_rn(y - fy);
    hi = (uint32_t)__bfloat16_as_ushort(hx) | ((uint32_t)__bfloat16_as_ushort(hy) << 16);
    lo = (uint32_t)__bfloat16_as_ushort(lx) | ((uint32_t)__bfloat16_as_ushort(ly) << 16);
}

// D += A(16x16,row) * B(16x8,col)  bf16 -> fp32
__device__ __forceinline__ void mma16816(float* c, uint32_t a0, uint32_t a1,
                                         uint32_t a2, uint32_t a3,
                                         uint32_t b0, uint32_t b1) {
    asm volatile(
        "mma.sync.aligned.m16n8k16.row.col.f32.bf16.bf16.f32 "
        "{%0,%1,%2,%3}, {%4,%5,%6,%7}, {%8,%9}, {%0,%1,%2,%3};"
        : "+f"(c[0]), "+f"(c[1]), "+f"(c[2]), "+f"(c[3])
        : "r"(a0), "r"(a1), "r"(a2), "r"(a3), "r"(b0), "r"(b1));
}

__device__ __forceinline__ void grid_barrier(unsigned* local_sense) {
    __threadfence();
    __syncthreads();
    if (threadIdx.x == 0) {
        const unsigned s = *local_sense ^ 1u;
        *local_sense = s;
        if (atomicAdd(&g_bar_count, 1) == GRID_SCAN - 1) {
            g_bar_count = 0;
            __threadfence();
            g_bar_sense = s;
        } else {
            while (g_bar_sense != s) { }
        }
    }
    __syncthreads();
}

// ===========================================================================
// Kernel A: gates_pre[m][n] = sum_k x[m][k]*W[n][k] + bias[n]   (HMMA bf16x3)
// M=16384, N=4096, K=1024.  CTA tile 128x128, BK=32, 8 warps (4m x 2n).
// (unchanged from the passing R12 version)
// ===========================================================================
#define SA 40   // smem row stride (elems), padded: conflict-free fragment LDS

__global__ __launch_bounds__(256) void gemm_gates_mma(
    const float* __restrict__ x, const float* __restrict__ W,
    const float* __restrict__ bW, const float* __restrict__ bR)
{
    __shared__ uint16_t Ah[128 * SA], Al[128 * SA], Bh[128 * SA], Bl[128 * SA];
    __shared__ float biasS[128];

    const int tid  = threadIdx.x;
    const int lane = tid & 31;
    const int wid  = tid >> 5;
    const int wm   = wid & 3;     // 0..3 -> 32 m-rows each
    const int wn   = wid >> 2;    // 0..1 -> 64 n-cols each
    const int mblk = blockIdx.y;  // 0..127
    const int nblk = blockIdx.x;  // 0..31

    if (tid < 128) biasS[tid] = bW[nblk * 128 + tid] + bR[nblk * 128 + tid];

    const float* xb = x + (size_t)(mblk * 128) * IDIM;
    const float* wb = W + (size_t)(nblk * 128) * IDIM;

    float c[2][8][4];
#pragma unroll
    for (int mt = 0; mt < 2; mt++)
#pragma unroll
        for (int nt = 0; nt < 8; nt++)
#pragma unroll
            for (int q = 0; q < 4; q++) c[mt][nt][q] = 0.0f;

    for (int k0 = 0; k0 < IDIM; k0 += 32) {
        float4 av[4], bv[4];
#pragma unroll
        for (int i = 0; i < 4; i++) {
            const int idx = tid + 256 * i;
            const int row = idx >> 3, c4 = (idx & 7) * 4;
            av[i] = __ldg((const float4*)(xb + (size_t)row * IDIM + k0 + c4));
            bv[i] = __ldg((const float4*)(wb + (size_t)row * IDIM + k0 + c4));
        }
        __syncthreads();
#pragma unroll
        for (int i = 0; i < 4; i++) {
            const int idx = tid + 256 * i;
            const int row = idx >> 3, c4 = (idx & 7) * 4;
            uint32_t h0, l0, h1, l1;
            split2(av[i].x, av[i].y, h0, l0);
            split2(av[i].z, av[i].w, h1, l1);
            *(uint2*)&Ah[row * SA + c4] = make_uint2(h0, h1);
            *(uint2*)&Al[row * SA + c4] = make_uint2(l0, l1);
            split2(bv[i].x, bv[i].y, h0, l0);
            split2(bv[i].z, bv[i].w, h1, l1);
            *(uint2*)&Bh[row * SA + c4] = make_uint2(h0, h1);
            *(uint2*)&Bl[row * SA + c4] = make_uint2(l0, l1);
        }
        __syncthreads();

#pragma unroll
        for (int kk = 0; kk < 32; kk += 16) {
            uint32_t ah[2][4], al[2][4];
#pragma unroll
            for (int mt = 0; mt < 2; mt++) {
                const int ra = wm * 32 + mt * 16 + (lane >> 2);
                const int ca = kk + (lane & 3) * 2;
                ah[mt][0] = *(const uint32_t*)&Ah[ra * SA + ca];
                ah[mt][1] = *(const uint32_t*)&Ah[(ra + 8) * SA + ca];
                ah[mt][2] = *(const uint32_t*)&Ah[ra * SA + ca + 8];
                ah[mt][3] = *(const uint32_t*)&Ah[(ra + 8) * SA + ca + 8];
                al[mt][0] = *(const uint32_t*)&Al[ra * SA + ca];
                al[mt][1] = *(const uint32_t*)&Al[(ra + 8) * SA + ca];
                al[mt][2] = *(const uint32_t*)&Al[ra * SA + ca + 8];
                al[mt][3] = *(const uint32_t*)&Al[(ra + 8) * SA + ca + 8];
            }
#pragma unroll
            for (int nt = 0; nt < 8; nt++) {
                const int rb = wn * 64 + nt * 8 + (lane >> 2);
                const int cb = kk + (lane & 3) * 2;
                const uint32_t bh0 = *(const uint32_t*)&Bh[rb * SA + cb];
                const uint32_t bh1 = *(const uint32_t*)&Bh[rb * SA + cb + 8];
                const uint32_t bl0 = *(const uint32_t*)&Bl[rb * SA + cb];
                const uint32_t bl1 = *(const uint32_t*)&Bl[rb * SA + cb + 8];
#pragma unroll
                for (int mt = 0; mt < 2; mt++) {
                    mma16816(c[mt][nt], ah[mt][0], ah[mt][1], ah[mt][2], ah[mt][3], bh0, bh1);
                    mma16816(c[mt][nt], al[mt][0], al[mt][1], al[mt][2], al[mt][3], bh0, bh1);
                    mma16816(c[mt][nt], ah[mt][0], ah[mt][1], ah[mt][2], ah[mt][3], bl0, bl1);
                }
            }
        }
        __syncthreads();
    }

#pragma unroll
    for (int mt = 0; mt < 2; mt++) {
#pragma unroll
        for (int nt = 0; nt < 8; nt++) {
            const int r0 = mblk * 128 + wm * 32 + mt * 16 + (lane >> 2);
            const int nl = wn * 64 + nt * 8 + (lane & 3) * 2;
            const float b0 = biasS[nl], b1 = biasS[nl + 1];
            *(float2*)&g_gates[(size_t)r0 * G4 + nblk * 128 + nl] =
                make_float2(c[mt][nt][0] + b0, c[mt][nt][1] + b1);
            *(float2*)&g_gates[(size_t)(r0 + 8) * G4 + nblk * 128 + nl] =
                make_float2(c[mt][nt][2] + b0, c[mt][nt][3] + b1);
        }
    }
}

// ===========================================================================
// Kernel B: persistent scan with HMMA recurrent GEMM.
//   CTA (mblk = bid&31, kc = bid>>5).  R chunk [128 g][256 k] in SMEM (bf16
//   hi/lo) for all 512 steps.  Per step:
//     prefetch gates_pre(t) into registers (hidden behind MMA + barrier)
//     phase 1 (warps 0-3, 32x32 tiles): part[b][h][gate] += y*R^T chunk
//     barrier; phase 2: combine (4x float4 part reads), c in REGISTER,
//     nonlinearities, write y/c out + y as bf16 hi/lo; barrier.
// ===========================================================================
#define SR 264  // smem row stride (elems) for scan tiles
#define SM_RH 0
#define SM_RL (128 * SR * 2)
#define SM_YH (2 * 128 * SR * 2)
#define SM_YL (2 * 128 * SR * 2 + 32 * SR * 2)
#define SM_SCAN_TOTAL (2 * 128 * SR * 2 + 2 * 32 * SR * 2)

__global__ __launch_bounds__(256) void lstm_scan(
    const float* __restrict__ R, const float* __restrict__ y0,
    const float* __restrict__ c0, float* __restrict__ yout,
    float* __restrict__ cout)
{
    extern __shared__ char smem[];
    uint16_t* Rh = (uint16_t*)(smem + SM_RH);
    uint16_t* Rl = (uint16_t*)(smem + SM_RL);
    uint16_t* Yh = (uint16_t*)(smem + SM_YH);
    uint16_t* Yl = (uint16_t*)(smem + SM_YL);
    __shared__ unsigned bar_sense;

    const int tid  = threadIdx.x;
    const int lane = tid & 31;
    const int wid  = tid >> 5;
    const int bid  = blockIdx.x;
    const int mblk = bid & 31;   // g-tile (128 gate-rows)
    const int kc   = bid >> 5;   // k-chunk (256)

    // This CTA's g-tile maps to one gate and one 128-wide h-range:
    const int gate_id = mblk >> 3;          // 0..3 (i,f,z,o)
    const int h_base  = (mblk & 7) * 128;   // h offset of local g-col 0

    if (tid == 0) bar_sense = 0;

    // ---- One-time: convert R chunk to bf16 hi/lo in SMEM ----
    {
        const float* Rb = R + (size_t)(mblk * 128) * HDIM + kc * 256;
#pragma unroll 8
        for (int i = 0; i < 64; i++) {
            const int p = tid + 256 * i;        // pair index, 16384 total
            const int row = p >> 7, cp = (p & 127) * 2;
            const float2 v = __ldg((const float2*)(Rb + (size_t)row * HDIM + cp));
            uint32_t hi, lo;
            split2(v.x, v.y, hi, lo);
            *(uint32_t*)&Rh[row * SR + cp] = hi;
            *(uint32_t*)&Rl[row * SR + cp] = lo;
        }
    }

    // ---- One-time: publish y0 as bf16 hi/lo; carry c in a register ----
    const int cn = bid * 256 + tid;   // 0..32767 -> (b,h)
    const int cb = cn >> 10;
    const int ch = cn & 1023;
    {
        const float v = y0[cn];
        const __nv_bfloat16 h = __float2bfloat16_rn(v);
        g_yhi[cn] = __bfloat16_as_ushort(h);
        g_ylo[cn] = __bfloat16_as_ushort(__float2bfloat16_rn(v - __bfloat162float(h)));
    }
    float c_cur = __ldg(c0 + cn);     // register-carried cell state

    grid_barrier(&bar_sense);   // barrier #1

    const float* gbase = g_gates + (size_t)cb * G4 + ch;

    for (int t = 0; t < T_STEPS; t++) {
        // -------- prefetch gates_pre(t) (hidden behind phase 1 + barrier) ----
        const float* gb = gbase + (size_t)t * BATCH * G4;
        const float pg_i = __ldg(gb);
        const float pg_f = __ldg(gb + HDIM);
        const float pg_z = __ldg(gb + 2 * HDIM);
        const float pg_o = __ldg(gb + 3 * HDIM);

        // -------- phase 1a: load y chunk (bf16 hi/lo) into SMEM --------
#pragma unroll 4
        for (int i = 0; i < 16; i++) {
            const int p = tid + 256 * i;        // 4096 pairs (32 x 128)
            const int b = p >> 7, cp = (p & 127) * 2;
            const int gs = b * HDIM + kc * 256 + cp;
            *(uint32_t*)&Yh[b * SR + cp] = __ldcg((const uint32_t*)(g_yhi + gs));
            *(uint32_t*)&Yl[b * SR + cp] = __ldcg((const uint32_t*)(g_ylo + gs));
        }
        __syncthreads();

        // -------- phase 1b: HMMA  D[b][g] (M=32, N=128, K=256), 4 warps ----
        if (wid < 4) {
            float c[2][4][4];
#pragma unroll
            for (int mt = 0; mt < 2; mt++)
#pragma unroll
                for (int nt = 0; nt < 4; nt++)
#pragma unroll
                    for (int q = 0; q < 4; q++) c[mt][nt][q] = 0.0f;

#pragma unroll 4
            for (int kk = 0; kk < 256; kk += 16) {
                uint32_t ah[2][4], al[2][4];
#pragma unroll
                for (int mt = 0; mt < 2; mt++) {
                    const int ra = mt * 16 + (lane >> 2);
                    const int ca = kk + (lane & 3) * 2;
                    ah[mt][0] = *(const uint32_t*)&Yh[ra * SR + ca];
                    ah[mt][1] = *(const uint32_t*)&Yh[(ra + 8) * SR + ca];
                    ah[mt][2] = *(const uint32_t*)&Yh[ra * SR + ca + 8];
                    ah[mt][3] = *(const uint32_t*)&Yh[(ra + 8) * SR + ca + 8];
                    al[mt][0] = *(const uint32_t*)&Yl[ra * SR + ca];
                    al[mt][1] = *(const uint32_t*)&Yl[(ra + 8) * SR + ca];
                    al[mt][2] = *(const uint32_t*)&Yl[ra * SR + ca + 8];
                    al[mt][3] = *(const uint32_t*)&Yl[(ra + 8) * SR + ca + 8];
                }
#pragma unroll
                for (int nt = 0; nt < 4; nt++) {
                    const int rb = wid * 32 + nt * 8 + (lane >> 2);
                    const int cb2 = kk + (lane & 3) * 2;
                    const uint32_t bh0 = *(const uint32_t*)&Rh[rb * SR + cb2];
                    const uint32_t bh1 = *(const uint32_t*)&Rh[rb * SR + cb2 + 8];
                    const uint32_t bl0 = *(const uint32_t*)&Rl[rb * SR + cb2];
                    const uint32_t bl1 = *(const uint32_t*)&Rl[rb * SR + cb2 + 8];
#pragma unroll
                    for (int mt = 0; mt < 2; mt++) {
                        mma16816(c[mt][nt], ah[mt][0], ah[mt][1], ah[mt][2], ah[mt][3], bh0, bh1);
                        mma16816(c[mt][nt], al[mt][0], al[mt][1], al[mt][2], al[mt][3], bh0, bh1);
                        mma16816(c[mt][nt], ah[mt][0], ah[mt][1], ah[mt][2], ah[mt][3], bl0, bl1);
                    }
                }
            }

            // store partials: layout [kc][b][h][gate]
#pragma unroll
            for (int mt = 0; mt < 2; mt++) {
#pragma unroll
                for (int nt = 0; nt < 4; nt++) {
                    const int b0 = mt * 16 + (lane >> 2);
                    const int h0 = h_base + wid * 32 + nt * 8 + (lane & 3) * 2;
                    const int i0 = ((kc * 32 + b0) << 12) + (h0 << 2) + gate_id;
                    g_part[i0]     = c[mt][nt][0];
                    g_part[i0 + 4] = c[mt][nt][1];
                    const int i1 = i0 + (8 << 12);
                    g_part[i1]     = c[mt][nt][2];
                    g_part[i1 + 4] = c[mt][nt][3];
                }
            }
        }

        grid_barrier(&bar_sense);

        // -------- phase 2: combine + nonlinearities + state update --------
        {
            const float4* pbase = (const float4*)g_part;
            const float4 p0 = __ldcg(pbase + ((0 * 32 + cb) << 10) + ch);
            const float4 p1 = __ldcg(pbase + ((1 * 32 + cb) << 10) + ch);
            const float4 p2 = __ldcg(pbase + ((2 * 32 + cb) << 10) + ch);
            const float4 p3 = __ldcg(pbase + ((3 * 32 + cb) << 10) + ch);

            const float gi = pg_i + p0.x + p1.x + p2.x + p3.x;
            const float gf = pg_f + p0.y + p1.y + p2.y + p3.y;
            const float gz = pg_z + p0.z + p1.z + p2.z + p3.z;
            const float go = pg_o + p0.w + p1.w + p2.w + p3.w;

            const float i_ = hsig(gi);
            const float f_ = hsig(gf);
            const float z_ = htanh(gz);
            const float o_ = hsig(go);

            c_cur = f_ * c_cur + i_ * z_;
            const float y_new = o_ * htanh(c_cur);

            yout[(size_t)t * BATCH * HDIM + cn] = y_new;
            cout[(size_t)t * BATCH * HDIM + cn] = c_cur;

            const __nv_bfloat16 h = __float2bfloat16_rn(y_new);
            g_yhi[cn] = __bfloat16_as_ushort(h);
            g_ylo[cn] = __bfloat16_as_ushort(
                __float2bfloat16_rn(y_new - __bfloat162float(h)));
        }

        grid_barrier(&bar_sense);
    }

    grid_barrier(&bar_sense);   // closing barrier -> even total (1026), clean replay
}

// ===========================================================================
// Launch: 2 graph nodes.
// ===========================================================================
extern "C" void kernel_launch(void* const* d_in, const int* in_sizes, int n_in,
                              void* d_out, int out_size)
{
    const float* y0 = (const float*)d_in[0];
    const float* c0 = (const float*)d_in[1];
    const float* x  = (const float*)d_in[2];
    const float* W  = (const float*)d_in[3];
    const float* R  = (const float*)d_in[4];
    const float* bW = (const float*)d_in[5];
    const float* bR = (const float*)d_in[6];

    float* yout = (float*)d_out;                                   // [T,B,H]
    float* cout = yout + (size_t)T_STEPS * BATCH * HDIM;           // [T,B,H]

    cudaFuncSetAttribute(lstm_scan,
                         cudaFuncAttributeMaxDynamicSharedMemorySize,
                         SM_SCAN_TOTAL);

    // Input projection for all timesteps (HMMA bf16x3)
    gemm_gates_mma<<<dim3(32, 128), 256>>>(x, W, bW, bR);

    // Full sequential scan in one persistent kernel (HMMA recurrent GEMM)
    lstm_scan<<<GRID_SCAN, 256, SM_SCAN_TOTAL>>>(R, y0, c0, yout, cout);
}

// round 17
// speedup vs baseline: 1.2539x; 1.2539x over previous
#include <cuda_runtime.h>
#include <cuda_bf16.h>
#include <cstdint>

#define T_STEPS 512
#define BATCH   32
#define IDIM    1024
#define HDIM    1024
#define G4      4096   // 4*HDIM
#define GRID_SCAN 128  // all CTAs co-resident (<= SM count)

// Scratch (static device arrays: allowed; no cudaMalloc anywhere)
__device__ float    g_gates[(size_t)T_STEPS * BATCH * G4];   // [t*B+b][g] (256 MB)
__device__ float    g_part[4 * BATCH * G4];                  // [kc][b][g] (2 MB)
__device__ uint16_t g_yhi[BATCH * HDIM];                     // y as bf16 hi
__device__ uint16_t g_ylo[BATCH * HDIM];                     // y as bf16 lo

// Grid-barrier state (sense-reversing; even barrier count per launch -> clean replays)
__device__ int               g_bar_count = 0;
__device__ volatile unsigned g_bar_sense = 0;

__device__ __forceinline__ float hsig(float x) {
    return fminf(fmaxf(x * (1.0f / 6.0f) + 0.5f, 0.0f), 1.0f);
}
__device__ __forceinline__ float htanh(float x) {
    return fminf(fmaxf(x, -1.0f), 1.0f);
}

// Split two floats into packed bf16 hi-pair and lo-pair (v = hi + lo)
__device__ __forceinline__ void split2(float x, float y, uint32_t& hi, uint32_t& lo) {
    const __nv_bfloat16 hx = __float2bfloat16_rn(x);
    const __nv_bfloat16 hy = __float2bfloat16_rn(y);
    const float fx = __bfloat162float(hx);
    const float fy = __bfloat162float(hy);
    const __nv_bfloat16 lx = __float2bfloat16_rn(x - fx);
    const __nv_bfloat16 ly = __float2bfloat16_rn(y - fy);
    hi = (uint32_t)__bfloat16_as_ushort(hx) | ((uint32_t)__bfloat16_as_ushort(hy) << 16);
    lo = (uint32_t)__bfloat16_as_ushort(lx) | ((uint32_t)__bfloat16_as_ushort(ly) << 16);
}

// D += A(16x16,row) * B(16x8,col)  bf16 -> fp32
__device__ __forceinline__ void mma16816(float* c, uint32_t a0, uint32_t a1,
                                         uint32_t a2, uint32_t a3,
                                         uint32_t b0, uint32_t b1) {
    asm volatile(
        "mma.sync.aligned.m16n8k16.row.col.f32.bf16.bf16.f32 "
        "{%0,%1,%2,%3}, {%4,%5,%6,%7}, {%8,%9}, {%0,%1,%2,%3};"
        : "+f"(c[0]), "+f"(c[1]), "+f"(c[2]), "+f"(c[3])
        : "r"(a0), "r"(a1), "r"(a2), "r"(a3), "r"(b0), "r"(b1));
}

__device__ __forceinline__ void grid_barrier(unsigned* local_sense) {
    __threadfence();
    __syncthreads();
    if (threadIdx.x == 0) {
        const unsigned s = *local_sense ^ 1u;
        *local_sense = s;
        if (atomicAdd(&g_bar_count, 1) == GRID_SCAN - 1) {
            g_bar_count = 0;
            __threadfence();
            g_bar_sense = s;
        } else {
            while (g_bar_sense != s) { }
        }
    }
    __syncthreads();
}

// ===========================================================================
// Kernel A: gates_pre[m][n] = sum_k x[m][k]*W[n][k] + bias[n]   (HMMA bf16x3)
// M=16384, N=4096, K=1024.  CTA tile 128x128, BK=32, 8 warps (4m x 2n).
// (unchanged from the passing R12 version)
// ===========================================================================
#define SA 40   // smem row stride (elems), padded: conflict-free fragment LDS

__global__ __launch_bounds__(256) void gemm_gates_mma(
    const float* __restrict__ x, const float* __restrict__ W,
    const float* __restrict__ bW, const float* __restrict__ bR)
{
    __shared__ uint16_t Ah[128 * SA], Al[128 * SA], Bh[128 * SA], Bl[128 * SA];
    __shared__ float biasS[128];

    const int tid  = threadIdx.x;
    const int lane = tid & 31;
    const int wid  = tid >> 5;
    const int wm   = wid & 3;     // 0..3 -> 32 m-rows each
    const int wn   = wid >> 2;    // 0..1 -> 64 n-cols each
    const int mblk = blockIdx.y;  // 0..127
    const int nblk = blockIdx.x;  // 0..31

    if (tid < 128) biasS[tid] = bW[nblk * 128 + tid] + bR[nblk * 128 + tid];

    const float* xb = x + (size_t)(mblk * 128) * IDIM;
    const float* wb = W + (size_t)(nblk * 128) * IDIM;

    float c[2][8][4];
#pragma unroll
    for (int mt = 0; mt < 2; mt++)
#pragma unroll
        for (int nt = 0; nt < 8; nt++)
#pragma unroll
            for (int q = 0; q < 4; q++) c[mt][nt][q] = 0.0f;

    for (int k0 = 0; k0 < IDIM; k0 += 32) {
        float4 av[4], bv[4];
#pragma unroll
        for (int i = 0; i < 4; i++) {
            const int idx = tid + 256 * i;
            const int row = idx >> 3, c4 = (idx & 7) * 4;
            av[i] = __ldg((const float4*)(xb + (size_t)row * IDIM + k0 + c4));
            bv[i] = __ldg((const float4*)(wb + (size_t)row * IDIM + k0 + c4));
        }
        __syncthreads();
#pragma unroll
        for (int i = 0; i < 4; i++) {
            const int idx = tid + 256 * i;
            const int row = idx >> 3, c4 = (idx & 7) * 4;
            uint32_t h0, l0, h1, l1;
            split2(av[i].x, av[i].y, h0, l0);
            split2(av[i].z, av[i].w, h1, l1);
            *(uint2*)&Ah[row * SA + c4] = make_uint2(h0, h1);
            *(uint2*)&Al[row * SA + c4] = make_uint2(l0, l1);
            split2(bv[i].x, bv[i].y, h0, l0);
            split2(bv[i].z, bv[i].w, h1, l1);
            *(uint2*)&Bh[row * SA + c4] = make_uint2(h0, h1);
            *(uint2*)&Bl[row * SA + c4] = make_uint2(l0, l1);
        }
        __syncthreads();

#pragma unroll
        for (int kk = 0; kk < 32; kk += 16) {
            uint32_t ah[2][4], al[2][4];
#pragma unroll
            for (int mt = 0; mt < 2; mt++) {
                const int ra = wm * 32 + mt * 16 + (lane >> 2);
                const int ca = kk + (lane & 3) * 2;
                ah[mt][0] = *(const uint32_t*)&Ah[ra * SA + ca];
                ah[mt][1] = *(const uint32_t*)&Ah[(ra + 8) * SA + ca];
                ah[mt][2] = *(const uint32_t*)&Ah[ra * SA + ca + 8];
                ah[mt][3] = *(const uint32_t*)&Ah[(ra + 8) * SA + ca + 8];
                al[mt][0] = *(const uint32_t*)&Al[ra * SA + ca];
                al[mt][1] = *(const uint32_t*)&Al[(ra + 8) * SA + ca];
                al[mt][2] = *(const uint32_t*)&Al[ra * SA + ca + 8];
                al[mt][3] = *(const uint32_t*)&Al[(ra + 8) * SA + ca + 8];
            }
#pragma unroll
            for (int nt = 0; nt < 8; nt++) {
                const int rb = wn * 64 + nt * 8 + (lane >> 2);
                const int cb = kk + (lane & 3) * 2;
                const uint32_t bh0 = *(const uint32_t*)&Bh[rb * SA + cb];
                const uint32_t bh1 = *(const uint32_t*)&Bh[rb * SA + cb + 8];
                const uint32_t bl0 = *(const uint32_t*)&Bl[rb * SA + cb];
                const uint32_t bl1 = *(const uint32_t*)&Bl[rb * SA + cb + 8];
#pragma unroll
                for (int mt = 0; mt < 2; mt++) {
                    mma16816(c[mt][nt], ah[mt][0], ah[mt][1], ah[mt][2], ah[mt][3], bh0, bh1);
                    mma16816(c[mt][nt], al[mt][0], al[mt][1], al[mt][2], al[mt][3], bh0, bh1);
                    mma16816(c[mt][nt], ah[mt][0], ah[mt][1], ah[mt][2], ah[mt][3], bl0, bl1);
                }
            }
        }
        __syncthreads();
    }

#pragma unroll
    for (int mt = 0; mt < 2; mt++) {
#pragma unroll
        for (int nt = 0; nt < 8; nt++) {
            const int r0 = mblk * 128 + wm * 32 + mt * 16 + (lane >> 2);
            const int nl = wn * 64 + nt * 8 + (lane & 3) * 2;
            const float b0 = biasS[nl], b1 = biasS[nl + 1];
            *(float2*)&g_gates[(size_t)r0 * G4 + nblk * 128 + nl] =
                make_float2(c[mt][nt][0] + b0, c[mt][nt][1] + b1);
            *(float2*)&g_gates[(size_t)(r0 + 8) * G4 + nblk * 128 + nl] =
                make_float2(c[mt][nt][2] + b0, c[mt][nt][3] + b1);
        }
    }
}

// ===========================================================================
// Kernel B: persistent scan with HMMA recurrent GEMM.
// Structure identical to the PASSING R12 version (8 MMA warps, [kc][b][g]
// part layout, coalesced float2 stores).  Exactly two additions:
//   (1) cell state carried in a register (no cprev reload per step)
//   (2) gates_pre(t) prefetched at the top of phase 1 (DRAM latency hidden
//       behind y-load + MMA + grid barrier instead of exposed in phase 2)
// ===========================================================================
#define SR 264  // smem row stride (elems) for scan tiles
#define SM_RH 0
#define SM_RL (128 * SR * 2)
#define SM_YH (2 * 128 * SR * 2)
#define SM_YL (2 * 128 * SR * 2 + 32 * SR * 2)
#define SM_SCAN_TOTAL (2 * 128 * SR * 2 + 2 * 32 * SR * 2)

__global__ __launch_bounds__(256) void lstm_scan(
    const float* __restrict__ R, const float* __restrict__ y0,
    const float* __restrict__ c0, float* __restrict__ yout,
    float* __restrict__ cout)
{
    extern __shared__ char smem[];
    uint16_t* Rh = (uint16_t*)(smem + SM_RH);
    uint16_t* Rl = (uint16_t*)(smem + SM_RL);
    uint16_t* Yh = (uint16_t*)(smem + SM_YH);
    uint16_t* Yl = (uint16_t*)(smem + SM_YL);
    __shared__ unsigned bar_sense;

    const int tid  = threadIdx.x;
    const int lane = tid & 31;
    const int wid  = tid >> 5;
    const int bid  = blockIdx.x;
    const int mblk = bid & 31;   // g-tile (128 gate-rows)
    const int kc   = bid >> 5;   // k-chunk (256)

    if (tid == 0) bar_sense = 0;

    // ---- One-time: convert R chunk to bf16 hi/lo in SMEM ----
    {
        const float* Rb = R + (size_t)(mblk * 128) * HDIM + kc * 256;
#pragma unroll 8
        for (int i = 0; i < 64; i++) {
            const int p = tid + 256 * i;        // pair index, 16384 total
            const int row = p >> 7, cp = (p & 127) * 2;
            const float2 v = __ldg((const float2*)(Rb + (size_t)row * HDIM + cp));
            uint32_t hi, lo;
            split2(v.x, v.y, hi, lo);
            *(uint32_t*)&Rh[row * SR + cp] = hi;
            *(uint32_t*)&Rl[row * SR + cp] = lo;
        }
    }

    // ---- One-time: publish y0 as bf16 hi/lo; carry c in a register ----
    const int cn = bid * 256 + tid;   // 0..32767 -> (b,h)
    const int cb = cn >> 10;
    const int ch = cn & 1023;
    {
        const float v = y0[cn];
        const __nv_bfloat16 h = __float2bfloat16_rn(v);
        g_yhi[cn] = __bfloat16_as_ushort(h);
        g_ylo[cn] = __bfloat16_as_ushort(__float2bfloat16_rn(v - __bfloat162float(h)));
    }
    float c_cur = __ldg(c0 + cn);     // register-carried cell state

    grid_barrier(&bar_sense);   // barrier #1

    float* part = g_part + (size_t)kc * BATCH * G4;
    const float* gbase = g_gates + (size_t)cb * G4 + ch;

    for (int t = 0; t < T_STEPS; t++) {
        // -------- prefetch gates_pre(t): latency hidden behind phase 1 ------
        const float* gb = gbase + (size_t)t * BATCH * G4;
        const float pg_i = __ldg(gb);
        const float pg_f = __ldg(gb + HDIM);
        const float pg_z = __ldg(gb + 2 * HDIM);
        const float pg_o = __ldg(gb + 3 * HDIM);

        // -------- phase 1a: load y chunk (bf16 hi/lo) into SMEM --------
#pragma unroll 4
        for (int i = 0; i < 16; i++) {
            const int p = tid + 256 * i;        // 4096 pairs (32 x 128)
            const int b = p >> 7, cp = (p & 127) * 2;
            const int gs = b * HDIM + kc * 256 + cp;
            *(uint32_t*)&Yh[b * SR + cp] = __ldcg((const uint32_t*)(g_yhi + gs));
            *(uint32_t*)&Yl[b * SR + cp] = __ldcg((const uint32_t*)(g_ylo + gs));
        }
        __syncthreads();

        // -------- phase 1b: HMMA  D[b][g] (M=32, N=128, K=256), 8 warps ----
        // warp wid owns g columns [wid*16, wid*16+16): 2 n8-subtiles, both m16 tiles
        float c[2][2][4];
#pragma unroll
        for (int mt = 0; mt < 2; mt++)
#pragma unroll
            for (int nt = 0; nt < 2; nt++)
#pragma unroll
                for (int q = 0; q < 4; q++) c[mt][nt][q] = 0.0f;

#pragma unroll 4
        for (int kk = 0; kk < 256; kk += 16) {
            uint32_t ah[2][4], al[2][4];
#pragma unroll
            for (int mt = 0; mt < 2; mt++) {
                const int ra = mt * 16 + (lane >> 2);
                const int ca = kk + (lane & 3) * 2;
                ah[mt][0] = *(const uint32_t*)&Yh[ra * SR + ca];
                ah[mt][1] = *(const uint32_t*)&Yh[(ra + 8) * SR + ca];
                ah[mt][2] = *(const uint32_t*)&Yh[ra * SR + ca + 8];
                ah[mt][3] = *(const uint32_t*)&Yh[(ra + 8) * SR + ca + 8];
                al[mt][0] = *(const uint32_t*)&Yl[ra * SR + ca];
                al[mt][1] = *(const uint32_t*)&Yl[(ra + 8) * SR + ca];
                al[mt][2] = *(const uint32_t*)&Yl[ra * SR + ca + 8];
                al[mt][3] = *(const uint32_t*)&Yl[(ra + 8) * SR + ca + 8];
            }
#pragma unroll
            for (int nt = 0; nt < 2; nt++) {
                const int rb = wid * 16 + nt * 8 + (lane >> 2);
                const int cb2 = kk + (lane & 3) * 2;
                const uint32_t bh0 = *(const uint32_t*)&Rh[rb * SR + cb2];
                const uint32_t bh1 = *(const uint32_t*)&Rh[rb * SR + cb2 + 8];
                const uint32_t bl0 = *(const uint32_t*)&Rl[rb * SR + cb2];
                const uint32_t bl1 = *(const uint32_t*)&Rl[rb * SR + cb2 + 8];
#pragma unroll
                for (int mt = 0; mt < 2; mt++) {
                    mma16816(c[mt][nt], ah[mt][0], ah[mt][1], ah[mt][2], ah[mt][3], bh0, bh1);
                    mma16816(c[mt][nt], al[mt][0], al[mt][1], al[mt][2], al[mt][3], bh0, bh1);
                    mma16816(c[mt][nt], ah[mt][0], ah[mt][1], ah[mt][2], ah[mt][3], bl0, bl1);
                }
            }
        }

        // store partials: c0,c1 -> b=(mt*16+lane/4), g pair; c2,c3 -> b+8
#pragma unroll
        for (int mt = 0; mt < 2; mt++) {
#pragma unroll
            for (int nt = 0; nt < 2; nt++) {
                const int b0 = mt * 16 + (lane >> 2);
                const int g0 = mblk * 128 + wid * 16 + nt * 8 + (lane & 3) * 2;
                *(float2*)&part[(size_t)b0 * G4 + g0] =
                    make_float2(c[mt][nt][0], c[mt][nt][1]);
                *(float2*)&part[(size_t)(b0 + 8) * G4 + g0] =
                    make_float2(c[mt][nt][2], c[mt][nt][3]);
            }
        }

        grid_barrier(&bar_sense);

        // -------- phase 2: combine + nonlinearities + state update --------
        {
            float gi = pg_i;
            float gf = pg_f;
            float gz = pg_z;
            float go = pg_o;

#pragma unroll
            for (int q = 0; q < 4; q++) {
                const float* p = g_part + (size_t)q * BATCH * G4 + (size_t)cb * G4;
                gi += __ldcg(p + ch);
                gf += __ldcg(p + HDIM + ch);
                gz += __ldcg(p + 2 * HDIM + ch);
                go += __ldcg(p + 3 * HDIM + ch);
            }

            const float i_ = hsig(gi);
            const float f_ = hsig(gf);
            const float z_ = htanh(gz);
            const float o_ = hsig(go);

            c_cur = f_ * c_cur + i_ * z_;
            const float y_new = o_ * htanh(c_cur);

            yout[(size_t)t * BATCH * HDIM + cn] = y_new;
            cout[(size_t)t * BATCH * HDIM + cn] = c_cur;

            const __nv_bfloat16 h = __float2bfloat16_rn(y_new);
            g_yhi[cn] = __bfloat16_as_ushort(h);
            g_ylo[cn] = __bfloat16_as_ushort(
                __float2bfloat16_rn(y_new - __bfloat162float(h)));
        }

        grid_barrier(&bar_sense);
    }

    grid_barrier(&bar_sense);   // closing barrier -> even total (1026), clean replay
}

// ===========================================================================
// Launch: 2 graph nodes.
// ===========================================================================
extern "C" void kernel_launch(void* const* d_in, const int* in_sizes, int n_in,
                              void* d_out, int out_size)
{
    const float* y0 = (const float*)d_in[0];
    const float* c0 = (const float*)d_in[1];
    const float* x  = (const float*)d_in[2];
    const float* W  = (const float*)d_in[3];
    const float* R  = (const float*)d_in[4];
    const float* bW = (const float*)d_in[5];
    const float* bR = (const float*)d_in[6];

    float* yout = (float*)d_out;                                   // [T,B,H]
    float* cout = yout + (size_t)T_STEPS * BATCH * HDIM;           // [T,B,H]

    cudaFuncSetAttribute(lstm_scan,
                         cudaFuncAttributeMaxDynamicSharedMemorySize,
                         SM_SCAN_TOTAL);

    // Input projection for all timesteps (HMMA bf16x3)
    gemm_gates_mma<<<dim3(32, 128), 256>>>(x, W, bW, bR);

    // Full sequential scan in one persistent kernel (HMMA recurrent GEMM)
    lstm_scan<<<GRID_SCAN, 256, SM_SCAN_TOTAL>>>(R, y0, c0, yout, cout);
}